// round 8
// baseline (speedup 1.0000x reference)
#include <cuda_runtime.h>
#include <cstdint>

// ---------------------------------------------------------------------------
// Fused: h = x @ w^T + b ; instance-norm over OUT ; out = (norm(h)+y)*y
// Single GEMM pass + Gram-identity row stats.
// R8 (from R7): y/out use streaming cache ops (keep L1 for w); epilogue param
// loads hoisted (12 float2/chunk); precompute consolidated into ONE
// atomics-free kernel (2 launches total per call).
// ---------------------------------------------------------------------------

#define DEVINL __device__ __forceinline__

static constexpr int IN      = 128;
static constexpr int OUT     = 2048;
static constexpr int MTILE   = 64;
static constexpr int NCHUNK  = 128;
static constexpr int NCHUNKS = OUT / NCHUNK;   // 16
static constexpr int THREADS = 256;            // 8 warps: 2m x 4n
static constexpr int TS      = 132;            // smem row stride (floats)

// SMEM layout (floats)
static constexpr int X_OFF    = 0;                // 64 x 132
static constexpr int MEAN_OFF = X_OFF + MTILE * TS;
static constexpr int DOTC_OFF = MEAN_OFF + MTILE;
static constexpr int SQ_OFF   = DOTC_OFF + MTILE;
static constexpr int ISTD_OFF = SQ_OFF + MTILE;
static constexpr int TOTAL_F  = ISTD_OFF + MTILE;

// ---- device scratch ----
__device__ __align__(16) float g_wp[OUT * IN];   // permuted + tf32-truncated w
__device__ __align__(16) float g_G[IN * IN];     // Gram, permuted cols
__device__ __align__(16) float g_c[IN];          // permuted
__device__ __align__(16) float g_sw[IN];         // permuted
__device__ float g_db[2];

DEVINL float tf32_trunc(float f) {
    return __uint_as_float(__float_as_uint(f) & 0xFFFFE000u);
}
DEVINL uint32_t f2tf32(float f) {
    uint32_t r;
    asm("cvt.rna.tf32.f32 %0, %1;" : "=r"(r) : "f"(f));
    return r;
}

DEVINL void mma_tf32(float* c, uint32_t a0, uint32_t a1, uint32_t a2, uint32_t a3,
                     uint32_t b0, uint32_t b1) {
    asm volatile(
        "mma.sync.aligned.m16n8k8.row.col.f32.tf32.tf32.f32 "
        "{%0,%1,%2,%3}, {%4,%5,%6,%7}, {%8,%9}, {%0,%1,%2,%3};"
        : "+f"(c[0]), "+f"(c[1]), "+f"(c[2]), "+f"(c[3])
        : "r"(a0), "r"(a1), "r"(a2), "r"(a3), "r"(b0), "r"(b1));
}

// Column permutation: logical k -> packed index within a 128-float row.
DEVINL int permc(int k) {
    int tg = k & 3, h = (k >> 2) & 1, s = k >> 3;
    int i = 2 * s + h;
    return ((i >> 2) * 4 + tg) * 4 + (i & 3);
}
// SMEM float offset of logical (row, k) with skew slot' = (sl+3r)&31.
DEVINL int xoff_perm(int r, int k) {
    int p = permc(k);
    int sl = p >> 2;
    int seg = (sl + 3 * r) & 31;
    return r * TS + seg * 4 + (p & 3);
}

// ---------------- single precompute kernel (atomics-free) ----------------
// grid = 64, block = 256.
//  Phase A: block t permutes+truncates w rows [32t, 32t+32) into g_wp.
//  Phase B: block t computes G rows [2t, 2t+2) with a full K=2048 loop;
//           block 0 also computes c = sum b_j w'_j, sw = sum w'_j, db.
__global__ __launch_bounds__(256, 1)
void gram2_kernel(const float* __restrict__ w, const float* __restrict__ b) {
    __shared__ float ws[32][IN];
    __shared__ float bs[32];
    const int tid = threadIdx.x;
    const int t   = blockIdx.x;

    // ---- Phase A ----
    {
        const int rbase = t * 32;
        #pragma unroll
        for (int it = 0; it < 4; ++it) {
            int i  = it * 256 + tid;
            int j  = i >> 5;
            int c4 = (i & 31) * 4;
            float4 v = *reinterpret_cast<const float4*>(w + (size_t)(rbase + j) * IN + c4);
            ws[j][c4 + 0] = tf32_trunc(v.x);
            ws[j][c4 + 1] = tf32_trunc(v.y);
            ws[j][c4 + 2] = tf32_trunc(v.z);
            ws[j][c4 + 3] = tf32_trunc(v.w);
        }
        __syncthreads();
        #pragma unroll
        for (int it = 0; it < 16; ++it) {
            int i = it * 256 + tid;
            int j = i >> 7;
            int q = i & 127;
            int sl = q >> 2, pos = q & 3;
            int i2 = (sl >> 2) * 4 + pos;
            int k  = 8 * (i2 >> 1) + 4 * (i2 & 1) + (sl & 3);
            g_wp[(size_t)(rbase + j) * IN + q] = ws[j][k];
        }
        __syncthreads();
    }

    // ---- Phase B ----
    const int kq = tid >> 7;          // 0..1 (uniform per warp)
    const int l  = tid & 127;
    const int kglob = 2 * t + kq;
    float acc = 0.0f;
    float cacc = 0.0f, swacc = 0.0f;
    float db0 = 0.0f, db1 = 0.0f;

    for (int jb = 0; jb < OUT / 32; ++jb) {
        const int rbase = jb * 32;
        #pragma unroll
        for (int it = 0; it < 4; ++it) {
            int i  = it * 256 + tid;
            int j  = i >> 5;
            int c4 = (i & 31) * 4;
            float4 v = *reinterpret_cast<const float4*>(w + (size_t)(rbase + j) * IN + c4);
            ws[j][c4 + 0] = tf32_trunc(v.x);
            ws[j][c4 + 1] = tf32_trunc(v.y);
            ws[j][c4 + 2] = tf32_trunc(v.z);
            ws[j][c4 + 3] = tf32_trunc(v.w);
        }
        if (t == 0 && tid < 32) bs[tid] = b[rbase + tid];
        __syncthreads();

        #pragma unroll 8
        for (int j = 0; j < 32; ++j)
            acc += ws[j][kglob] * ws[j][l];

        if (t == 0) {
            if (tid < 128) {
                #pragma unroll 8
                for (int j = 0; j < 32; ++j) {
                    float v = ws[j][tid];
                    cacc  += bs[j] * v;
                    swacc += v;
                }
            } else if (tid == 128) {
                #pragma unroll 8
                for (int j = 0; j < 32; ++j) {
                    db0 += bs[j] * bs[j];
                    db1 += bs[j];
                }
            }
        }
        __syncthreads();
    }

    g_G[kglob * IN + permc(l)] = acc;
    if (t == 0) {
        if (tid < 128) {
            g_c[permc(tid)]  = cacc;
            g_sw[permc(tid)] = swacc;
        } else if (tid == 128) {
            g_db[0] = db0;
            g_db[1] = db1;
        }
    }
}

// ---------------- main kernel ----------------

DEVINL void load_x_tile(float* dst, const float* __restrict__ g, int tid) {
    #pragma unroll
    for (int it = 0; it < (MTILE * 32) / THREADS; ++it) {
        int i  = it * THREADS + tid;
        int r  = i >> 5;
        int c4 = (i & 31) * 4;
        float4 v = *reinterpret_cast<const float4*>(g + (size_t)r * IN + c4);
        float vv[4] = {v.x, v.y, v.z, v.w};
        #pragma unroll
        for (int e = 0; e < 4; ++e)
            dst[xoff_perm(r, c4 + e)] = __uint_as_float(f2tf32(vv[e]));
    }
}

// Warp-tile 32x32 GEMM, K=128. a: LDS.128 (conflict-free). b: LDG.128 from
// permuted gmem rows (L1/L2 resident), pipelined j -> j+1.
DEVINL void compute_chunk(const float* __restrict__ xs, const float* __restrict__ wg,
                          int m0, int n0, int g, int tig, float acc[2][4][4]) {
    #pragma unroll
    for (int mt = 0; mt < 2; ++mt)
        #pragma unroll
        for (int nt = 0; nt < 4; ++nt)
            #pragma unroll
            for (int q = 0; q < 4; ++q)
                acc[mt][nt][q] = 0.0f;

    float4 bfn[4];
    #pragma unroll
    for (int nt = 0; nt < 4; ++nt)
        bfn[nt] = __ldg(reinterpret_cast<const float4*>(
                        wg + (size_t)(n0 + nt * 8 + g) * IN + tig * 4));

    #pragma unroll
    for (int j = 0; j < 8; ++j) {
        float4 bf[4];
        #pragma unroll
        for (int nt = 0; nt < 4; ++nt) bf[nt] = bfn[nt];
        if (j < 7) {
            #pragma unroll
            for (int nt = 0; nt < 4; ++nt)
                bfn[nt] = __ldg(reinterpret_cast<const float4*>(
                                wg + (size_t)(n0 + nt * 8 + g) * IN + ((j + 1) * 4 + tig) * 4));
        }

        float4 af[2][2];
        #pragma unroll
        for (int mt = 0; mt < 2; ++mt) {
            const int r1 = m0 + mt * 16 + g;
            const int r2 = r1 + 8;
            af[mt][0] = *reinterpret_cast<const float4*>(
                            xs + r1 * TS + (((j * 4 + tig + 3 * r1) & 31) * 4));
            af[mt][1] = *reinterpret_cast<const float4*>(
                            xs + r2 * TS + (((j * 4 + tig + 3 * r2) & 31) * 4));
        }

        #pragma unroll
        for (int mt = 0; mt < 2; ++mt)
            #pragma unroll
            for (int nt = 0; nt < 4; ++nt)
                mma_tf32(acc[mt][nt],
                         __float_as_uint(af[mt][0].x), __float_as_uint(af[mt][1].x),
                         __float_as_uint(af[mt][0].y), __float_as_uint(af[mt][1].y),
                         __float_as_uint(bf[nt].x),   __float_as_uint(bf[nt].y));
        #pragma unroll
        for (int mt = 0; mt < 2; ++mt)
            #pragma unroll
            for (int nt = 0; nt < 4; ++nt)
                mma_tf32(acc[mt][nt],
                         __float_as_uint(af[mt][0].z), __float_as_uint(af[mt][1].z),
                         __float_as_uint(af[mt][0].w), __float_as_uint(af[mt][1].w),
                         __float_as_uint(bf[nt].z),   __float_as_uint(bf[nt].w));
    }
}

__global__ __launch_bounds__(THREADS, 2)
void fused_lin_inorm_kernel(const float* __restrict__ x,
                            const float* __restrict__ y,
                            const float* __restrict__ lb,
                            const float* __restrict__ nw,
                            const float* __restrict__ nb,
                            float* __restrict__ out) {
    __shared__ float sm[TOTAL_F];
    const int tid  = threadIdx.x;
    const int wid  = tid >> 5;
    const int lane = tid & 31;
    const int g    = lane >> 2;
    const int tig  = lane & 3;
    const int m0   = (wid >> 2) * 32;
    const int n0   = (wid & 3) * 32;
    const size_t row0 = (size_t)blockIdx.x * MTILE;

    float* xs = sm + X_OFF;

    if (tid < MTILE) sm[SQ_OFF + tid] = 0.0f;
    load_x_tile(xs, x + row0 * IN, tid);
    __syncthreads();

    if (tid < MTILE) {
        const int r = tid;
        float dm = 0.0f, dc = 0.0f;
        #pragma unroll 8
        for (int sl = 0; sl < 32; ++sl) {
            int seg = (sl + 3 * r) & 31;
            float4 xv = *reinterpret_cast<const float4*>(xs + r * TS + seg * 4);
            float4 sv = *reinterpret_cast<const float4*>(g_sw + sl * 4);
            float4 cv = *reinterpret_cast<const float4*>(g_c + sl * 4);
            dm += xv.x * sv.x + xv.y * sv.y + xv.z * sv.z + xv.w * sv.w;
            dc += xv.x * cv.x + xv.y * cv.y + xv.z * cv.z + xv.w * cv.w;
        }
        sm[MEAN_OFF + r] = (dm + g_db[1]) * (1.0f / OUT);
        sm[DOTC_OFF + r] = dc;
    }

    // ---- stats chunk: Z = x' @ G ; rsq = sum Z .* x' per row ----
    {
        float acc[2][4][4];
        compute_chunk(xs, g_G, m0, n0, g, tig, acc);

        float rsq[4] = {0.f, 0.f, 0.f, 0.f};
        #pragma unroll
        for (int mt = 0; mt < 2; ++mt)
            #pragma unroll
            for (int h = 0; h < 2; ++h) {
                const int r = m0 + mt * 16 + h * 8 + g;
                #pragma unroll
                for (int nt = 0; nt < 4; ++nt)
                    #pragma unroll
                    for (int p = 0; p < 2; ++p) {
                        int col = n0 + nt * 8 + tig * 2 + p;
                        rsq[mt * 2 + h] += acc[mt][nt][h * 2 + p] * xs[xoff_perm(r, col)];
                    }
            }
        #pragma unroll
        for (int j = 0; j < 4; ++j) {
            rsq[j] += __shfl_xor_sync(0xffffffffu, rsq[j], 1);
            rsq[j] += __shfl_xor_sync(0xffffffffu, rsq[j], 2);
        }
        if (tig == 0) {
            #pragma unroll
            for (int j = 0; j < 4; ++j) {
                int r = m0 + (j >> 1) * 16 + (j & 1) * 8 + g;
                atomicAdd(&sm[SQ_OFF + r], rsq[j]);
            }
        }
    }
    __syncthreads();

    if (tid < MTILE) {
        float sumsq = sm[SQ_OFF + tid] + 2.0f * sm[DOTC_OFF + tid] + g_db[0];
        float mean  = sm[MEAN_OFF + tid];
        float var   = sumsq * (1.0f / OUT) - mean * mean;
        sm[ISTD_OFF + tid] = rsqrtf(var + 1e-5f);
    }
    __syncthreads();

    float meanv[4], istdv[4];
    #pragma unroll
    for (int j = 0; j < 4; ++j) {
        int r = m0 + (j >> 1) * 16 + (j & 1) * 8 + g;
        meanv[j] = sm[MEAN_OFF + r];
        istdv[j] = sm[ISTD_OFF + r];
    }

    // ---------------- main loop: 16 chunks, NO barriers ----------------
    #pragma unroll 1
    for (int ch = 0; ch < NCHUNKS; ++ch) {
        float acc[2][4][4];
        compute_chunk(xs, g_wp + (size_t)ch * NCHUNK * IN, m0, n0, g, tig, acc);

        const int gcb = ch * NCHUNK + n0 + tig * 2;

        // Hoisted per-chunk column params (L1-resident).
        float2 lbv[4], nwv[4], nbv[4];
        #pragma unroll
        for (int nt = 0; nt < 4; ++nt) {
            lbv[nt] = __ldg(reinterpret_cast<const float2*>(lb + gcb + nt * 8));
            nwv[nt] = __ldg(reinterpret_cast<const float2*>(nw + gcb + nt * 8));
            nbv[nt] = __ldg(reinterpret_cast<const float2*>(nb + gcb + nt * 8));
        }

        #pragma unroll
        for (int mt = 0; mt < 2; ++mt)
            #pragma unroll
            for (int h = 0; h < 2; ++h) {
                int j = mt * 2 + h;
                size_t grow = row0 + (size_t)(m0 + mt * 16 + h * 8 + g);
                const float* yr  = y   + grow * OUT + gcb;
                float*       orw = out + grow * OUT + gcb;
                #pragma unroll
                for (int nt = 0; nt < 4; ++nt) {
                    float2 yv = __ldcs(reinterpret_cast<const float2*>(yr + nt * 8));
                    float v0 = acc[mt][nt][h * 2 + 0] + lbv[nt].x;
                    float v1 = acc[mt][nt][h * 2 + 1] + lbv[nt].y;
                    float nm0 = (v0 - meanv[j]) * istdv[j] * nwv[nt].x + nbv[nt].x;
                    float nm1 = (v1 - meanv[j]) * istdv[j] * nwv[nt].y + nbv[nt].y;
                    float2 ov;
                    ov.x = (nm0 + yv.x) * yv.x;
                    ov.y = (nm1 + yv.y) * yv.y;
                    __stcs(reinterpret_cast<float2*>(orw + nt * 8), ov);
                }
            }
    }
}

extern "C" void kernel_launch(void* const* d_in, const int* in_sizes, int n_in,
                              void* d_out, int out_size) {
    (void)n_in; (void)out_size;
    const float* x  = (const float*)d_in[0];
    const float* y  = (const float*)d_in[1];
    const float* w  = (const float*)d_in[2];
    const float* lb = (const float*)d_in[3];
    const float* nw = (const float*)d_in[4];
    const float* nb = (const float*)d_in[5];
    float* out = (float*)d_out;

    const int rows = in_sizes[0] / IN;   // 32768
    const int grid = rows / MTILE;       // 512

    gram2_kernel<<<64, 256>>>(w, lb);
    fused_lin_inorm_kernel<<<grid, THREADS>>>(x, y, lb, nw, nb, out);
}

// round 9
// speedup vs baseline: 1.3716x; 1.3716x over previous
#include <cuda_runtime.h>
#include <cstdint>

// ---------------------------------------------------------------------------
// Fused: h = x @ w^T + b ; instance-norm over OUT ; out = (norm(h)+y)*y
// Single GEMM pass + Gram-identity row stats.
// R9 = R7 (241us baseline: barrier-free main loop, w via LDG.128 from
// permuted gmem, x in conflict-free permuted smem, 2 CTAs/SM) + y-prefetch:
// each chunk's y values are loaded into registers BEFORE the mma chain so
// their DRAM latency overlaps compute instead of serializing the epilogue.
// ldcs/stcs and gram2 from R8 reverted (both regressed).
// ---------------------------------------------------------------------------

#define DEVINL __device__ __forceinline__

static constexpr int IN      = 128;
static constexpr int OUT     = 2048;
static constexpr int MTILE   = 64;
static constexpr int NCHUNK  = 128;
static constexpr int NCHUNKS = OUT / NCHUNK;   // 16
static constexpr int THREADS = 256;            // 8 warps: 2m x 4n
static constexpr int TS      = 132;            // smem row stride (floats)

// SMEM layout (floats)
static constexpr int X_OFF    = 0;                // 64 x 132
static constexpr int MEAN_OFF = X_OFF + MTILE * TS;
static constexpr int DOTC_OFF = MEAN_OFF + MTILE;
static constexpr int SQ_OFF   = DOTC_OFF + MTILE;
static constexpr int ISTD_OFF = SQ_OFF + MTILE;
static constexpr int TOTAL_F  = ISTD_OFF + MTILE;

// ---- device scratch ----
__device__ __align__(16) float g_wp[OUT * IN];   // permuted + tf32-truncated w
__device__ __align__(16) float g_G[IN * IN];     // Gram, permuted cols
__device__ __align__(16) float g_c[IN];          // permuted
__device__ __align__(16) float g_sw[IN];         // permuted
__device__ float g_db[2];

DEVINL float tf32_trunc(float f) {
    return __uint_as_float(__float_as_uint(f) & 0xFFFFE000u);
}
DEVINL uint32_t f2tf32(float f) {
    uint32_t r;
    asm("cvt.rna.tf32.f32 %0, %1;" : "=r"(r) : "f"(f));
    return r;
}

DEVINL void mma_tf32(float* c, uint32_t a0, uint32_t a1, uint32_t a2, uint32_t a3,
                     uint32_t b0, uint32_t b1) {
    asm volatile(
        "mma.sync.aligned.m16n8k8.row.col.f32.tf32.tf32.f32 "
        "{%0,%1,%2,%3}, {%4,%5,%6,%7}, {%8,%9}, {%0,%1,%2,%3};"
        : "+f"(c[0]), "+f"(c[1]), "+f"(c[2]), "+f"(c[3])
        : "r"(a0), "r"(a1), "r"(a2), "r"(a3), "r"(b0), "r"(b1));
}

// Column permutation: logical k -> packed index within a 128-float row.
DEVINL int permc(int k) {
    int tg = k & 3, h = (k >> 2) & 1, s = k >> 3;
    int i = 2 * s + h;
    return ((i >> 2) * 4 + tg) * 4 + (i & 3);
}
// SMEM float offset of logical (row, k) with skew slot' = (sl+3r)&31.
DEVINL int xoff_perm(int r, int k) {
    int p = permc(k);
    int sl = p >> 2;
    int seg = (sl + 3 * r) & 31;
    return r * TS + seg * 4 + (p & 3);
}

// ---------------- precompute kernels (R7 versions) ----------------

__global__ void zero_scratch_kernel() {
    int i = blockIdx.x * blockDim.x + threadIdx.x;
    if (i < IN * IN) g_G[i] = 0.0f;
    if (i < IN) { g_c[i] = 0.0f; g_sw[i] = 0.0f; }
    if (i < 2)  g_db[i] = 0.0f;
}

__global__ __launch_bounds__(256, 1)
void gram_kernel(const float* __restrict__ w, const float* __restrict__ b) {
    __shared__ float ws[32][IN];
    __shared__ float bs[32];
    const int tid   = threadIdx.x;
    const int jbase = blockIdx.x * 32;

    #pragma unroll
    for (int it = 0; it < 4; ++it) {
        int i  = it * 256 + tid;
        int j  = i >> 5;
        int c4 = (i & 31) * 4;
        float4 v = *reinterpret_cast<const float4*>(w + (size_t)(jbase + j) * IN + c4);
        ws[j][c4 + 0] = tf32_trunc(v.x);
        ws[j][c4 + 1] = tf32_trunc(v.y);
        ws[j][c4 + 2] = tf32_trunc(v.z);
        ws[j][c4 + 3] = tf32_trunc(v.w);
    }
    if (tid < 32) bs[tid] = b[jbase + tid];
    __syncthreads();

    // Emit permuted w rows (coalesced 128-float rows).
    #pragma unroll
    for (int it = 0; it < 16; ++it) {
        int i = it * 256 + tid;              // 4096 elements
        int j = i >> 7;
        int q = i & 127;                     // dest packed index
        int sl = q >> 2, pos = q & 3;
        int i2 = (sl >> 2) * 4 + pos;
        int k  = 8 * (i2 >> 1) + 4 * (i2 & 1) + (sl & 3);
        g_wp[(size_t)(jbase + j) * IN + q] = ws[j][k];
    }

    const int k     = tid & 127;
    const int lbase = (tid >> 7) * 64;
    float acc[64];
    #pragma unroll
    for (int l = 0; l < 64; ++l) acc[l] = 0.0f;
    float ck = 0.0f, swk = 0.0f;

    for (int j = 0; j < 32; ++j) {
        float wk = ws[j][k];
        #pragma unroll
        for (int l = 0; l < 64; ++l) acc[l] += wk * ws[j][lbase + l];
        ck  += bs[j] * wk;
        swk += wk;
    }
    #pragma unroll
    for (int l = 0; l < 64; ++l)
        atomicAdd(&g_G[k * IN + permc(lbase + l)], acc[l]);
    if (tid < IN) {
        atomicAdd(&g_c[permc(k)], ck);
        atomicAdd(&g_sw[permc(k)], swk);
    }
    if (tid < 32) {
        atomicAdd(&g_db[0], bs[tid] * bs[tid]);
        atomicAdd(&g_db[1], bs[tid]);
    }
}

// ---------------- main kernel ----------------

DEVINL void load_x_tile(float* dst, const float* __restrict__ g, int tid) {
    #pragma unroll
    for (int it = 0; it < (MTILE * 32) / THREADS; ++it) {
        int i  = it * THREADS + tid;
        int r  = i >> 5;
        int c4 = (i & 31) * 4;
        float4 v = *reinterpret_cast<const float4*>(g + (size_t)r * IN + c4);
        float vv[4] = {v.x, v.y, v.z, v.w};
        #pragma unroll
        for (int e = 0; e < 4; ++e)
            dst[xoff_perm(r, c4 + e)] = __uint_as_float(f2tf32(vv[e]));
    }
}

// Warp-tile 32x32 GEMM, K=128. a: LDS.128 (conflict-free). b: LDG.128 from
// permuted gmem rows (L1/L2 resident), pipelined j -> j+1.
DEVINL void compute_chunk(const float* __restrict__ xs, const float* __restrict__ wg,
                          int m0, int n0, int g, int tig, float acc[2][4][4]) {
    #pragma unroll
    for (int mt = 0; mt < 2; ++mt)
        #pragma unroll
        for (int nt = 0; nt < 4; ++nt)
            #pragma unroll
            for (int q = 0; q < 4; ++q)
                acc[mt][nt][q] = 0.0f;

    float4 bfn[4];
    #pragma unroll
    for (int nt = 0; nt < 4; ++nt)
        bfn[nt] = __ldg(reinterpret_cast<const float4*>(
                        wg + (size_t)(n0 + nt * 8 + g) * IN + tig * 4));

    #pragma unroll
    for (int j = 0; j < 8; ++j) {
        float4 bf[4];
        #pragma unroll
        for (int nt = 0; nt < 4; ++nt) bf[nt] = bfn[nt];
        if (j < 7) {
            #pragma unroll
            for (int nt = 0; nt < 4; ++nt)
                bfn[nt] = __ldg(reinterpret_cast<const float4*>(
                                wg + (size_t)(n0 + nt * 8 + g) * IN + ((j + 1) * 4 + tig) * 4));
        }

        float4 af[2][2];
        #pragma unroll
        for (int mt = 0; mt < 2; ++mt) {
            const int r1 = m0 + mt * 16 + g;
            const int r2 = r1 + 8;
            af[mt][0] = *reinterpret_cast<const float4*>(
                            xs + r1 * TS + (((j * 4 + tig + 3 * r1) & 31) * 4));
            af[mt][1] = *reinterpret_cast<const float4*>(
                            xs + r2 * TS + (((j * 4 + tig + 3 * r2) & 31) * 4));
        }

        #pragma unroll
        for (int mt = 0; mt < 2; ++mt)
            #pragma unroll
            for (int nt = 0; nt < 4; ++nt)
                mma_tf32(acc[mt][nt],
                         __float_as_uint(af[mt][0].x), __float_as_uint(af[mt][1].x),
                         __float_as_uint(af[mt][0].y), __float_as_uint(af[mt][1].y),
                         __float_as_uint(bf[nt].x),   __float_as_uint(bf[nt].y));
        #pragma unroll
        for (int mt = 0; mt < 2; ++mt)
            #pragma unroll
            for (int nt = 0; nt < 4; ++nt)
                mma_tf32(acc[mt][nt],
                         __float_as_uint(af[mt][0].z), __float_as_uint(af[mt][1].z),
                         __float_as_uint(af[mt][0].w), __float_as_uint(af[mt][1].w),
                         __float_as_uint(bf[nt].z),   __float_as_uint(bf[nt].w));
    }
}

__global__ __launch_bounds__(THREADS, 2)
void fused_lin_inorm_kernel(const float* __restrict__ x,
                            const float* __restrict__ y,
                            const float* __restrict__ lb,
                            const float* __restrict__ nw,
                            const float* __restrict__ nb,
                            float* __restrict__ out) {
    __shared__ float sm[TOTAL_F];
    const int tid  = threadIdx.x;
    const int wid  = tid >> 5;
    const int lane = tid & 31;
    const int g    = lane >> 2;
    const int tig  = lane & 3;
    const int m0   = (wid >> 2) * 32;
    const int n0   = (wid & 3) * 32;
    const size_t row0 = (size_t)blockIdx.x * MTILE;

    float* xs = sm + X_OFF;

    if (tid < MTILE) sm[SQ_OFF + tid] = 0.0f;
    load_x_tile(xs, x + row0 * IN, tid);
    __syncthreads();

    if (tid < MTILE) {
        const int r = tid;
        float dm = 0.0f, dc = 0.0f;
        #pragma unroll 8
        for (int sl = 0; sl < 32; ++sl) {
            int seg = (sl + 3 * r) & 31;
            float4 xv = *reinterpret_cast<const float4*>(xs + r * TS + seg * 4);
            float4 sv = *reinterpret_cast<const float4*>(g_sw + sl * 4);
            float4 cv = *reinterpret_cast<const float4*>(g_c + sl * 4);
            dm += xv.x * sv.x + xv.y * sv.y + xv.z * sv.z + xv.w * sv.w;
            dc += xv.x * cv.x + xv.y * cv.y + xv.z * cv.z + xv.w * cv.w;
        }
        sm[MEAN_OFF + r] = (dm + g_db[1]) * (1.0f / OUT);
        sm[DOTC_OFF + r] = dc;
    }

    // ---- stats chunk: Z = x' @ G ; rsq = sum Z .* x' per row ----
    {
        float acc[2][4][4];
        compute_chunk(xs, g_G, m0, n0, g, tig, acc);

        float rsq[4] = {0.f, 0.f, 0.f, 0.f};
        #pragma unroll
        for (int mt = 0; mt < 2; ++mt)
            #pragma unroll
            for (int h = 0; h < 2; ++h) {
                const int r = m0 + mt * 16 + h * 8 + g;
                #pragma unroll
                for (int nt = 0; nt < 4; ++nt)
                    #pragma unroll
                    for (int p = 0; p < 2; ++p) {
                        int col = n0 + nt * 8 + tig * 2 + p;
                        rsq[mt * 2 + h] += acc[mt][nt][h * 2 + p] * xs[xoff_perm(r, col)];
                    }
            }
        #pragma unroll
        for (int j = 0; j < 4; ++j) {
            rsq[j] += __shfl_xor_sync(0xffffffffu, rsq[j], 1);
            rsq[j] += __shfl_xor_sync(0xffffffffu, rsq[j], 2);
        }
        if (tig == 0) {
            #pragma unroll
            for (int j = 0; j < 4; ++j) {
                int r = m0 + (j >> 1) * 16 + (j & 1) * 8 + g;
                atomicAdd(&sm[SQ_OFF + r], rsq[j]);
            }
        }
    }
    __syncthreads();

    if (tid < MTILE) {
        float sumsq = sm[SQ_OFF + tid] + 2.0f * sm[DOTC_OFF + tid] + g_db[0];
        float mean  = sm[MEAN_OFF + tid];
        float var   = sumsq * (1.0f / OUT) - mean * mean;
        sm[ISTD_OFF + tid] = rsqrtf(var + 1e-5f);
    }
    __syncthreads();

    float meanv[4], istdv[4];
    #pragma unroll
    for (int j = 0; j < 4; ++j) {
        int r = m0 + (j >> 1) * 16 + (j & 1) * 8 + g;
        meanv[j] = sm[MEAN_OFF + r];
        istdv[j] = sm[ISTD_OFF + r];
    }

    // ---------------- main loop: 16 chunks, NO barriers ----------------
    #pragma unroll 1
    for (int ch = 0; ch < NCHUNKS; ++ch) {
        const int gcb = ch * NCHUNK + n0 + tig * 2;

        // Prefetch this chunk's y values BEFORE the mma chain so the DRAM
        // latency overlaps compute instead of serializing the epilogue.
        float2 yv[2][2][4];
        #pragma unroll
        for (int mt = 0; mt < 2; ++mt)
            #pragma unroll
            for (int h = 0; h < 2; ++h) {
                size_t grow = row0 + (size_t)(m0 + mt * 16 + h * 8 + g);
                const float* yr = y + grow * OUT + gcb;
                #pragma unroll
                for (int nt = 0; nt < 4; ++nt)
                    yv[mt][h][nt] = __ldg(reinterpret_cast<const float2*>(yr + nt * 8));
            }

        float acc[2][4][4];
        compute_chunk(xs, g_wp + (size_t)ch * NCHUNK * IN, m0, n0, g, tig, acc);

        #pragma unroll
        for (int mt = 0; mt < 2; ++mt)
            #pragma unroll
            for (int h = 0; h < 2; ++h) {
                int j = mt * 2 + h;
                size_t grow = row0 + (size_t)(m0 + mt * 16 + h * 8 + g);
                float* orw = out + grow * OUT + gcb;
                #pragma unroll
                for (int nt = 0; nt < 4; ++nt) {
                    float2 lbv = __ldg(reinterpret_cast<const float2*>(lb + gcb + nt * 8));
                    float2 nwv = __ldg(reinterpret_cast<const float2*>(nw + gcb + nt * 8));
                    float2 nbv = __ldg(reinterpret_cast<const float2*>(nb + gcb + nt * 8));
                    float2 yy  = yv[mt][h][nt];
                    float v0 = acc[mt][nt][h * 2 + 0] + lbv.x;
                    float v1 = acc[mt][nt][h * 2 + 1] + lbv.y;
                    float nm0 = (v0 - meanv[j]) * istdv[j] * nwv.x + nbv.x;
                    float nm1 = (v1 - meanv[j]) * istdv[j] * nwv.y + nbv.y;
                    float2 ov;
                    ov.x = (nm0 + yy.x) * yy.x;
                    ov.y = (nm1 + yy.y) * yy.y;
                    *reinterpret_cast<float2*>(orw + nt * 8) = ov;
                }
            }
    }
}

extern "C" void kernel_launch(void* const* d_in, const int* in_sizes, int n_in,
                              void* d_out, int out_size) {
    (void)n_in; (void)out_size;
    const float* x  = (const float*)d_in[0];
    const float* y  = (const float*)d_in[1];
    const float* w  = (const float*)d_in[2];
    const float* lb = (const float*)d_in[3];
    const float* nw = (const float*)d_in[4];
    const float* nb = (const float*)d_in[5];
    float* out = (float*)d_out;

    const int rows = in_sizes[0] / IN;   // 32768
    const int grid = rows / MTILE;       // 512

    zero_scratch_kernel<<<64, 256>>>();
    gram_kernel<<<OUT / 32, 256>>>(w, lb);
    fused_lin_inorm_kernel<<<grid, THREADS>>>(x, y, lb, nw, nb, out);
}

// round 10
// speedup vs baseline: 1.5490x; 1.1294x over previous
#include <cuda_runtime.h>
#include <cstdint>

// ---------------------------------------------------------------------------
// Fused: h = x @ w^T + b ; instance-norm over OUT ; out = (norm(h)+y)*y
// Single GEMM pass + Gram-identity row stats.
// R10 = R7/R9 baseline + coalesced epilogue: each warp stages its 32x32 acc
// tile through a warp-private padded smem buffer (syncwarp only), then does
// y/out as float4 ops on 32 contiguous rows x 32 contiguous cols (4 lines per
// instruction instead of 8 scattered lines per float2). 4x fewer epilogue L1
// wavefronts -- the measured R8 bottleneck (L1 58.9%, epilogue-dominated).
// ---------------------------------------------------------------------------

#define DEVINL __device__ __forceinline__

static constexpr int IN      = 128;
static constexpr int OUT     = 2048;
static constexpr int MTILE   = 64;
static constexpr int NCHUNK  = 128;
static constexpr int NCHUNKS = OUT / NCHUNK;   // 16
static constexpr int THREADS = 256;            // 8 warps: 2m x 4n
static constexpr int TS      = 132;            // x tile row stride (floats)
static constexpr int SSTR    = 40;             // stage tile row stride (floats)

// SMEM layout (floats)
static constexpr int X_OFF     = 0;                      // 64 x 132
static constexpr int STAGE_OFF = X_OFF + MTILE * TS;     // 8 warps x 32 x 40
static constexpr int MEAN_OFF  = STAGE_OFF + 8 * 32 * SSTR;
static constexpr int DOTC_OFF  = MEAN_OFF + MTILE;
static constexpr int SQ_OFF    = DOTC_OFF + MTILE;
static constexpr int ISTD_OFF  = SQ_OFF + MTILE;
static constexpr int TOTAL_F   = ISTD_OFF + MTILE;       // ~76 KB

// ---- device scratch ----
__device__ __align__(16) float g_wp[OUT * IN];   // permuted + tf32-truncated w
__device__ __align__(16) float g_G[IN * IN];     // Gram, permuted cols
__device__ __align__(16) float g_c[IN];          // permuted
__device__ __align__(16) float g_sw[IN];         // permuted
__device__ float g_db[2];

DEVINL float tf32_trunc(float f) {
    return __uint_as_float(__float_as_uint(f) & 0xFFFFE000u);
}
DEVINL uint32_t f2tf32(float f) {
    uint32_t r;
    asm("cvt.rna.tf32.f32 %0, %1;" : "=r"(r) : "f"(f));
    return r;
}

DEVINL void mma_tf32(float* c, uint32_t a0, uint32_t a1, uint32_t a2, uint32_t a3,
                     uint32_t b0, uint32_t b1) {
    asm volatile(
        "mma.sync.aligned.m16n8k8.row.col.f32.tf32.tf32.f32 "
        "{%0,%1,%2,%3}, {%4,%5,%6,%7}, {%8,%9}, {%0,%1,%2,%3};"
        : "+f"(c[0]), "+f"(c[1]), "+f"(c[2]), "+f"(c[3])
        : "r"(a0), "r"(a1), "r"(a2), "r"(a3), "r"(b0), "r"(b1));
}

// Column permutation: logical k -> packed index within a 128-float row.
DEVINL int permc(int k) {
    int tg = k & 3, h = (k >> 2) & 1, s = k >> 3;
    int i = 2 * s + h;
    return ((i >> 2) * 4 + tg) * 4 + (i & 3);
}
// SMEM float offset of logical (row, k) with skew slot' = (sl+3r)&31.
DEVINL int xoff_perm(int r, int k) {
    int p = permc(k);
    int sl = p >> 2;
    int seg = (sl + 3 * r) & 31;
    return r * TS + seg * 4 + (p & 3);
}

// ---------------- precompute kernels ----------------

__global__ void zero_scratch_kernel() {
    int i = blockIdx.x * blockDim.x + threadIdx.x;
    if (i < IN * IN) g_G[i] = 0.0f;
    if (i < IN) { g_c[i] = 0.0f; g_sw[i] = 0.0f; }
    if (i < 2)  g_db[i] = 0.0f;
}

__global__ __launch_bounds__(256, 1)
void gram_kernel(const float* __restrict__ w, const float* __restrict__ b) {
    __shared__ float ws[32][IN];
    __shared__ float bs[32];
    const int tid   = threadIdx.x;
    const int jbase = blockIdx.x * 32;

    #pragma unroll
    for (int it = 0; it < 4; ++it) {
        int i  = it * 256 + tid;
        int j  = i >> 5;
        int c4 = (i & 31) * 4;
        float4 v = *reinterpret_cast<const float4*>(w + (size_t)(jbase + j) * IN + c4);
        ws[j][c4 + 0] = tf32_trunc(v.x);
        ws[j][c4 + 1] = tf32_trunc(v.y);
        ws[j][c4 + 2] = tf32_trunc(v.z);
        ws[j][c4 + 3] = tf32_trunc(v.w);
    }
    if (tid < 32) bs[tid] = b[jbase + tid];
    __syncthreads();

    // Emit permuted w rows.
    #pragma unroll
    for (int it = 0; it < 16; ++it) {
        int i = it * 256 + tid;
        int j = i >> 7;
        int q = i & 127;
        int sl = q >> 2, pos = q & 3;
        int i2 = (sl >> 2) * 4 + pos;
        int k  = 8 * (i2 >> 1) + 4 * (i2 & 1) + (sl & 3);
        g_wp[(size_t)(jbase + j) * IN + q] = ws[j][k];
    }

    const int k     = tid & 127;
    const int lbase = (tid >> 7) * 64;
    float acc[64];
    #pragma unroll
    for (int l = 0; l < 64; ++l) acc[l] = 0.0f;
    float ck = 0.0f, swk = 0.0f;

    for (int j = 0; j < 32; ++j) {
        float wk = ws[j][k];
        #pragma unroll
        for (int l = 0; l < 64; ++l) acc[l] += wk * ws[j][lbase + l];
        ck  += bs[j] * wk;
        swk += wk;
    }
    #pragma unroll
    for (int l = 0; l < 64; ++l)
        atomicAdd(&g_G[k * IN + permc(lbase + l)], acc[l]);
    if (tid < IN) {
        atomicAdd(&g_c[permc(k)], ck);
        atomicAdd(&g_sw[permc(k)], swk);
    }
    if (tid < 32) {
        atomicAdd(&g_db[0], bs[tid] * bs[tid]);
        atomicAdd(&g_db[1], bs[tid]);
    }
}

// ---------------- main kernel ----------------

DEVINL void load_x_tile(float* dst, const float* __restrict__ g, int tid) {
    #pragma unroll
    for (int it = 0; it < (MTILE * 32) / THREADS; ++it) {
        int i  = it * THREADS + tid;
        int r  = i >> 5;
        int c4 = (i & 31) * 4;
        float4 v = *reinterpret_cast<const float4*>(g + (size_t)r * IN + c4);
        float vv[4] = {v.x, v.y, v.z, v.w};
        #pragma unroll
        for (int e = 0; e < 4; ++e)
            dst[xoff_perm(r, c4 + e)] = __uint_as_float(f2tf32(vv[e]));
    }
}

// Warp-tile 32x32 GEMM, K=128. a: LDS.128 (conflict-free). b: LDG.128 from
// permuted gmem rows (L1/L2 resident), pipelined j -> j+1.
DEVINL void compute_chunk(const float* __restrict__ xs, const float* __restrict__ wg,
                          int m0, int n0, int g, int tig, float acc[2][4][4]) {
    #pragma unroll
    for (int mt = 0; mt < 2; ++mt)
        #pragma unroll
        for (int nt = 0; nt < 4; ++nt)
            #pragma unroll
            for (int q = 0; q < 4; ++q)
                acc[mt][nt][q] = 0.0f;

    float4 bfn[4];
    #pragma unroll
    for (int nt = 0; nt < 4; ++nt)
        bfn[nt] = __ldg(reinterpret_cast<const float4*>(
                        wg + (size_t)(n0 + nt * 8 + g) * IN + tig * 4));

    #pragma unroll
    for (int j = 0; j < 8; ++j) {
        float4 bf[4];
        #pragma unroll
        for (int nt = 0; nt < 4; ++nt) bf[nt] = bfn[nt];
        if (j < 7) {
            #pragma unroll
            for (int nt = 0; nt < 4; ++nt)
                bfn[nt] = __ldg(reinterpret_cast<const float4*>(
                                wg + (size_t)(n0 + nt * 8 + g) * IN + ((j + 1) * 4 + tig) * 4));
        }

        float4 af[2][2];
        #pragma unroll
        for (int mt = 0; mt < 2; ++mt) {
            const int r1 = m0 + mt * 16 + g;
            const int r2 = r1 + 8;
            af[mt][0] = *reinterpret_cast<const float4*>(
                            xs + r1 * TS + (((j * 4 + tig + 3 * r1) & 31) * 4));
            af[mt][1] = *reinterpret_cast<const float4*>(
                            xs + r2 * TS + (((j * 4 + tig + 3 * r2) & 31) * 4));
        }

        #pragma unroll
        for (int mt = 0; mt < 2; ++mt)
            #pragma unroll
            for (int nt = 0; nt < 4; ++nt)
                mma_tf32(acc[mt][nt],
                         __float_as_uint(af[mt][0].x), __float_as_uint(af[mt][1].x),
                         __float_as_uint(af[mt][0].y), __float_as_uint(af[mt][1].y),
                         __float_as_uint(bf[nt].x),   __float_as_uint(bf[nt].y));
        #pragma unroll
        for (int mt = 0; mt < 2; ++mt)
            #pragma unroll
            for (int nt = 0; nt < 4; ++nt)
                mma_tf32(acc[mt][nt],
                         __float_as_uint(af[mt][0].z), __float_as_uint(af[mt][1].z),
                         __float_as_uint(af[mt][0].w), __float_as_uint(af[mt][1].w),
                         __float_as_uint(bf[nt].z),   __float_as_uint(bf[nt].w));
    }
}

__global__ __launch_bounds__(THREADS, 2)
void fused_lin_inorm_kernel(const float* __restrict__ x,
                            const float* __restrict__ y,
                            const float* __restrict__ lb,
                            const float* __restrict__ nw,
                            const float* __restrict__ nb,
                            float* __restrict__ out) {
    __shared__ float sm[TOTAL_F];
    const int tid  = threadIdx.x;
    const int wid  = tid >> 5;
    const int lane = tid & 31;
    const int g    = lane >> 2;
    const int tig  = lane & 3;
    const int m0   = (wid >> 2) * 32;
    const int n0   = (wid & 3) * 32;
    const size_t row0 = (size_t)blockIdx.x * MTILE;

    float* xs = sm + X_OFF;
    float* st = sm + STAGE_OFF + wid * (32 * SSTR);   // warp-private stage

    if (tid < MTILE) sm[SQ_OFF + tid] = 0.0f;
    load_x_tile(xs, x + row0 * IN, tid);
    __syncthreads();

    if (tid < MTILE) {
        const int r = tid;
        float dm = 0.0f, dc = 0.0f;
        #pragma unroll 8
        for (int sl = 0; sl < 32; ++sl) {
            int seg = (sl + 3 * r) & 31;
            float4 xv = *reinterpret_cast<const float4*>(xs + r * TS + seg * 4);
            float4 sv = *reinterpret_cast<const float4*>(g_sw + sl * 4);
            float4 cv = *reinterpret_cast<const float4*>(g_c + sl * 4);
            dm += xv.x * sv.x + xv.y * sv.y + xv.z * sv.z + xv.w * sv.w;
            dc += xv.x * cv.x + xv.y * cv.y + xv.z * cv.z + xv.w * cv.w;
        }
        sm[MEAN_OFF + r] = (dm + g_db[1]) * (1.0f / OUT);
        sm[DOTC_OFF + r] = dc;
    }

    // ---- stats chunk: Z = x' @ G ; rsq = sum Z .* x' per row ----
    {
        float acc[2][4][4];
        compute_chunk(xs, g_G, m0, n0, g, tig, acc);

        float rsq[4] = {0.f, 0.f, 0.f, 0.f};
        #pragma unroll
        for (int mt = 0; mt < 2; ++mt)
            #pragma unroll
            for (int h = 0; h < 2; ++h) {
                const int r = m0 + mt * 16 + h * 8 + g;
                #pragma unroll
                for (int nt = 0; nt < 4; ++nt)
                    #pragma unroll
                    for (int p = 0; p < 2; ++p) {
                        int col = n0 + nt * 8 + tig * 2 + p;
                        rsq[mt * 2 + h] += acc[mt][nt][h * 2 + p] * xs[xoff_perm(r, col)];
                    }
            }
        #pragma unroll
        for (int j = 0; j < 4; ++j) {
            rsq[j] += __shfl_xor_sync(0xffffffffu, rsq[j], 1);
            rsq[j] += __shfl_xor_sync(0xffffffffu, rsq[j], 2);
        }
        if (tig == 0) {
            #pragma unroll
            for (int j = 0; j < 4; ++j) {
                int r = m0 + (j >> 1) * 16 + (j & 1) * 8 + g;
                atomicAdd(&sm[SQ_OFF + r], rsq[j]);
            }
        }
    }
    __syncthreads();

    if (tid < MTILE) {
        float sumsq = sm[SQ_OFF + tid] + 2.0f * sm[DOTC_OFF + tid] + g_db[0];
        float mean  = sm[MEAN_OFF + tid];
        float var   = sumsq * (1.0f / OUT) - mean * mean;
        sm[ISTD_OFF + tid] = rsqrtf(var + 1e-5f);
    }
    __syncthreads();

    // Per-lane epilogue row constants for the coalesced readback:
    // iteration j covers stage rows j*4 + (lane>>3).
    const int rl = lane >> 3;       // 0..3
    const int cl = (lane & 7) * 4;  // 0,4,...,28
    float meanv[8], istdv[8];
    #pragma unroll
    for (int j = 0; j < 8; ++j) {
        int r = m0 + j * 4 + rl;
        meanv[j] = sm[MEAN_OFF + r];
        istdv[j] = sm[ISTD_OFF + r];
    }

    // ---------------- main loop: 16 chunks, NO CTA barriers ----------------
    #pragma unroll 1
    for (int ch = 0; ch < NCHUNKS; ++ch) {
        float acc[2][4][4];
        compute_chunk(xs, g_wp + (size_t)ch * NCHUNK * IN, m0, n0, g, tig, acc);

        // Stage the 32x32 acc tile into warp-private smem (conflict-free).
        #pragma unroll
        for (int mt = 0; mt < 2; ++mt)
            #pragma unroll
            for (int h = 0; h < 2; ++h)
                #pragma unroll
                for (int nt = 0; nt < 4; ++nt) {
                    float2 v = make_float2(acc[mt][nt][h * 2 + 0], acc[mt][nt][h * 2 + 1]);
                    *reinterpret_cast<float2*>(
                        st + (mt * 16 + h * 8 + g) * SSTR + nt * 8 + tig * 2) = v;
                }
        __syncwarp();

        // Coalesced readback + fused epilogue: float4 over 32 contiguous rows
        // x 32 contiguous cols (4 cache lines per instruction).
        const int cbase = ch * NCHUNK + n0;      // global col base (mult of 32)
        float4 lbv = __ldg(reinterpret_cast<const float4*>(lb + cbase + cl));
        float4 nwv = __ldg(reinterpret_cast<const float4*>(nw + cbase + cl));
        float4 nbv = __ldg(reinterpret_cast<const float4*>(nb + cbase + cl));

        #pragma unroll
        for (int j = 0; j < 8; ++j) {
            const int r = j * 4 + rl;            // local row 0..31
            float4 v = *reinterpret_cast<const float4*>(st + r * SSTR + cl);
            const size_t grow = row0 + (size_t)(m0 + r);
            float4 yv = __ldg(reinterpret_cast<const float4*>(y + grow * OUT + cbase + cl));
            const float mean = meanv[j], istd = istdv[j];
            float4 ov;
            float nm;
            nm = ((v.x + lbv.x) - mean) * istd * nwv.x + nbv.x; ov.x = (nm + yv.x) * yv.x;
            nm = ((v.y + lbv.y) - mean) * istd * nwv.y + nbv.y; ov.y = (nm + yv.y) * yv.y;
            nm = ((v.z + lbv.z) - mean) * istd * nwv.z + nbv.z; ov.z = (nm + yv.z) * yv.z;
            nm = ((v.w + lbv.w) - mean) * istd * nwv.w + nbv.w; ov.w = (nm + yv.w) * yv.w;
            *reinterpret_cast<float4*>(out + grow * OUT + cbase + cl) = ov;
        }
        __syncwarp();   // stage buffer reusable next chunk
    }
}

extern "C" void kernel_launch(void* const* d_in, const int* in_sizes, int n_in,
                              void* d_out, int out_size) {
    (void)n_in; (void)out_size;
    const float* x  = (const float*)d_in[0];
    const float* y  = (const float*)d_in[1];
    const float* w  = (const float*)d_in[2];
    const float* lb = (const float*)d_in[3];
    const float* nw = (const float*)d_in[4];
    const float* nb = (const float*)d_in[5];
    float* out = (float*)d_out;

    const int rows = in_sizes[0] / IN;   // 32768
    const int grid = rows / MTILE;       // 512

    zero_scratch_kernel<<<64, 256>>>();
    gram_kernel<<<OUT / 32, 256>>>(w, lb);
    fused_lin_inorm_kernel<<<grid, THREADS>>>(x, y, lb, nw, nb, out);
}

// round 11
// speedup vs baseline: 1.5982x; 1.0317x over previous
#include <cuda_runtime.h>
#include <cstdint>

// ---------------------------------------------------------------------------
// Fused: h = x @ w^T + b ; instance-norm over OUT ; out = (norm(h)+y)*y
// Single GEMM pass + Gram-identity row stats.
// R11 = R10 (215us: coalesced smem-staged epilogue) + fragment-major w layout:
// g_wp/g_G are emitted so each warp b-fragment LDG.128 reads 32 lanes x 16B
// CONTIGUOUS (4 sequential lines) instead of 8 scattered rows (8 lines).
// Halves b-side L1 wavefronts to the 128-line/chunk minimum.
//   layout: addr = row_group*1024 + j_iter*128 + (g*4+tig)*4   (floats)
//   where row_group = row/8, g = row%8, fragment float4 = logical k
//   {16j+tig, 16j+4+tig, 16j+8+tig, 16j+12+tig}.
// ---------------------------------------------------------------------------

#define DEVINL __device__ __forceinline__

static constexpr int IN      = 128;
static constexpr int OUT     = 2048;
static constexpr int MTILE   = 64;
static constexpr int NCHUNK  = 128;
static constexpr int NCHUNKS = OUT / NCHUNK;   // 16
static constexpr int THREADS = 256;            // 8 warps: 2m x 4n
static constexpr int TS      = 132;            // x tile row stride (floats)
static constexpr int SSTR    = 40;             // stage tile row stride (floats)

// SMEM layout (floats)
static constexpr int X_OFF     = 0;                      // 64 x 132
static constexpr int STAGE_OFF = X_OFF + MTILE * TS;     // 8 warps x 32 x 40
static constexpr int MEAN_OFF  = STAGE_OFF + 8 * 32 * SSTR;
static constexpr int DOTC_OFF  = MEAN_OFF + MTILE;
static constexpr int SQ_OFF    = DOTC_OFF + MTILE;
static constexpr int ISTD_OFF  = SQ_OFF + MTILE;
static constexpr int TOTAL_F   = ISTD_OFF + MTILE;       // ~76 KB

// ---- device scratch ----
__device__ __align__(16) float g_wp[OUT * IN];   // fragment-major truncated w
__device__ __align__(16) float g_G[IN * IN];     // Gram, fragment-major
__device__ __align__(16) float g_c[IN];          // permuted (x-layout order)
__device__ __align__(16) float g_sw[IN];         // permuted
__device__ float g_db[2];

DEVINL float tf32_trunc(float f) {
    return __uint_as_float(__float_as_uint(f) & 0xFFFFE000u);
}
DEVINL uint32_t f2tf32(float f) {
    uint32_t r;
    asm("cvt.rna.tf32.f32 %0, %1;" : "=r"(r) : "f"(f));
    return r;
}

DEVINL void mma_tf32(float* c, uint32_t a0, uint32_t a1, uint32_t a2, uint32_t a3,
                     uint32_t b0, uint32_t b1) {
    asm volatile(
        "mma.sync.aligned.m16n8k8.row.col.f32.tf32.tf32.f32 "
        "{%0,%1,%2,%3}, {%4,%5,%6,%7}, {%8,%9}, {%0,%1,%2,%3};"
        : "+f"(c[0]), "+f"(c[1]), "+f"(c[2]), "+f"(c[3])
        : "r"(a0), "r"(a1), "r"(a2), "r"(a3), "r"(b0), "r"(b1));
}

// Column permutation (x smem layout): logical k -> packed index in 128-float row.
DEVINL int permc(int k) {
    int tg = k & 3, h = (k >> 2) & 1, s = k >> 3;
    int i = 2 * s + h;
    return ((i >> 2) * 4 + tg) * 4 + (i & 3);
}
// x SMEM float offset of logical (row, k) with skew slot' = (sl+3r)&31.
DEVINL int xoff_perm(int r, int k) {
    int p = permc(k);
    int sl = p >> 2;
    int seg = (sl + 3 * r) & 31;
    return r * TS + seg * 4 + (p & 3);
}
// Fragment-major gmem float offset for (row, packed index p) within a 128-row
// chunk-local space: rg = row/8, j = (p>>2)>>2, tig = (p>>2)&3, pos = p&3.
DEVINL int wfrag_off(int row, int p) {
    int sl = p >> 2, pos = p & 3;
    int j = sl >> 2, tg = sl & 3;
    return (row >> 3) * 1024 + j * 128 + (((row & 7) * 4 + tg) * 4) + pos;
}

// ---------------- precompute kernels ----------------

__global__ void zero_scratch_kernel() {
    int i = blockIdx.x * blockDim.x + threadIdx.x;
    if (i < IN * IN) g_G[i] = 0.0f;
    if (i < IN) { g_c[i] = 0.0f; g_sw[i] = 0.0f; }
    if (i < 2)  g_db[i] = 0.0f;
}

__global__ __launch_bounds__(256, 1)
void gram_kernel(const float* __restrict__ w, const float* __restrict__ b) {
    __shared__ float ws[32][IN];
    __shared__ float bs[32];
    const int tid   = threadIdx.x;
    const int jbase = blockIdx.x * 32;   // multiple of 32 -> row groups align

    #pragma unroll
    for (int it = 0; it < 4; ++it) {
        int i  = it * 256 + tid;
        int j  = i >> 5;
        int c4 = (i & 31) * 4;
        float4 v = *reinterpret_cast<const float4*>(w + (size_t)(jbase + j) * IN + c4);
        ws[j][c4 + 0] = tf32_trunc(v.x);
        ws[j][c4 + 1] = tf32_trunc(v.y);
        ws[j][c4 + 2] = tf32_trunc(v.z);
        ws[j][c4 + 3] = tf32_trunc(v.w);
    }
    if (tid < 32) bs[tid] = b[jbase + tid];
    __syncthreads();

    // Emit fragment-major w rows.
    #pragma unroll
    for (int it = 0; it < 16; ++it) {
        int i = it * 256 + tid;
        int j = i >> 7;                     // local row
        int q = i & 127;                    // packed index p
        int sl = q >> 2, pos = q & 3;
        int i2 = (sl >> 2) * 4 + pos;
        int k  = 8 * (i2 >> 1) + 4 * (i2 & 1) + (sl & 3);   // logical k
        int R  = jbase + j;                 // global row
        // chunk-local row = R & 127 ; chunk base = (R>>7)*128*IN
        g_wp[(size_t)(R >> 7) * (128 * IN) + wfrag_off(R & 127, q)] = ws[j][k];
    }

    const int k     = tid & 127;
    const int lbase = (tid >> 7) * 64;
    float acc[64];
    #pragma unroll
    for (int l = 0; l < 64; ++l) acc[l] = 0.0f;
    float ck = 0.0f, swk = 0.0f;

    for (int j = 0; j < 32; ++j) {
        float wk = ws[j][k];
        #pragma unroll
        for (int l = 0; l < 64; ++l) acc[l] += wk * ws[j][lbase + l];
        ck  += bs[j] * wk;
        swk += wk;
    }
    // G row k (0..127): fragment-major within its single 128-row space.
    #pragma unroll
    for (int l = 0; l < 64; ++l)
        atomicAdd(&g_G[wfrag_off(k, permc(lbase + l))], acc[l]);
    if (tid < IN) {
        atomicAdd(&g_c[permc(k)], ck);
        atomicAdd(&g_sw[permc(k)], swk);
    }
    if (tid < 32) {
        atomicAdd(&g_db[0], bs[tid] * bs[tid]);
        atomicAdd(&g_db[1], bs[tid]);
    }
}

// ---------------- main kernel ----------------

DEVINL void load_x_tile(float* dst, const float* __restrict__ g, int tid) {
    #pragma unroll
    for (int it = 0; it < (MTILE * 32) / THREADS; ++it) {
        int i  = it * THREADS + tid;
        int r  = i >> 5;
        int c4 = (i & 31) * 4;
        float4 v = *reinterpret_cast<const float4*>(g + (size_t)r * IN + c4);
        float vv[4] = {v.x, v.y, v.z, v.w};
        #pragma unroll
        for (int e = 0; e < 4; ++e)
            dst[xoff_perm(r, c4 + e)] = __uint_as_float(f2tf32(vv[e]));
    }
}

// Warp-tile 32x32 GEMM, K=128. a: LDS.128 (conflict-free). b: LDG.128 from
// fragment-major gmem -- 32 lanes read 512B contiguous (4 lines/instr).
DEVINL void compute_chunk(const float* __restrict__ xs, const float* __restrict__ wg,
                          int m0, int n0, int g, int tig, int lane,
                          float acc[2][4][4]) {
    #pragma unroll
    for (int mt = 0; mt < 2; ++mt)
        #pragma unroll
        for (int nt = 0; nt < 4; ++nt)
            #pragma unroll
            for (int q = 0; q < 4; ++q)
                acc[mt][nt][q] = 0.0f;

    const int rg0   = n0 >> 3;          // first row group of this warp's slice
    const int lane4 = lane * 4;

    float4 bfn[4];
    #pragma unroll
    for (int nt = 0; nt < 4; ++nt)
        bfn[nt] = __ldg(reinterpret_cast<const float4*>(
                        wg + (rg0 + nt) * 1024 + lane4));

    #pragma unroll
    for (int j = 0; j < 8; ++j) {
        float4 bf[4];
        #pragma unroll
        for (int nt = 0; nt < 4; ++nt) bf[nt] = bfn[nt];
        if (j < 7) {
            #pragma unroll
            for (int nt = 0; nt < 4; ++nt)
                bfn[nt] = __ldg(reinterpret_cast<const float4*>(
                                wg + (rg0 + nt) * 1024 + (j + 1) * 128 + lane4));
        }

        float4 af[2][2];
        #pragma unroll
        for (int mt = 0; mt < 2; ++mt) {
            const int r1 = m0 + mt * 16 + g;
            const int r2 = r1 + 8;
            af[mt][0] = *reinterpret_cast<const float4*>(
                            xs + r1 * TS + (((j * 4 + tig + 3 * r1) & 31) * 4));
            af[mt][1] = *reinterpret_cast<const float4*>(
                            xs + r2 * TS + (((j * 4 + tig + 3 * r2) & 31) * 4));
        }

        #pragma unroll
        for (int mt = 0; mt < 2; ++mt)
            #pragma unroll
            for (int nt = 0; nt < 4; ++nt)
                mma_tf32(acc[mt][nt],
                         __float_as_uint(af[mt][0].x), __float_as_uint(af[mt][1].x),
                         __float_as_uint(af[mt][0].y), __float_as_uint(af[mt][1].y),
                         __float_as_uint(bf[nt].x),   __float_as_uint(bf[nt].y));
        #pragma unroll
        for (int mt = 0; mt < 2; ++mt)
            #pragma unroll
            for (int nt = 0; nt < 4; ++nt)
                mma_tf32(acc[mt][nt],
                         __float_as_uint(af[mt][0].z), __float_as_uint(af[mt][1].z),
                         __float_as_uint(af[mt][0].w), __float_as_uint(af[mt][1].w),
                         __float_as_uint(bf[nt].z),   __float_as_uint(bf[nt].w));
    }
}

__global__ __launch_bounds__(THREADS, 2)
void fused_lin_inorm_kernel(const float* __restrict__ x,
                            const float* __restrict__ y,
                            const float* __restrict__ lb,
                            const float* __restrict__ nw,
                            const float* __restrict__ nb,
                            float* __restrict__ out) {
    __shared__ float sm[TOTAL_F];
    const int tid  = threadIdx.x;
    const int wid  = tid >> 5;
    const int lane = tid & 31;
    const int g    = lane >> 2;
    const int tig  = lane & 3;
    const int m0   = (wid >> 2) * 32;
    const int n0   = (wid & 3) * 32;
    const size_t row0 = (size_t)blockIdx.x * MTILE;

    float* xs = sm + X_OFF;
    float* st = sm + STAGE_OFF + wid * (32 * SSTR);   // warp-private stage

    if (tid < MTILE) sm[SQ_OFF + tid] = 0.0f;
    load_x_tile(xs, x + row0 * IN, tid);
    __syncthreads();

    if (tid < MTILE) {
        const int r = tid;
        float dm = 0.0f, dc = 0.0f;
        #pragma unroll 8
        for (int sl = 0; sl < 32; ++sl) {
            int seg = (sl + 3 * r) & 31;
            float4 xv = *reinterpret_cast<const float4*>(xs + r * TS + seg * 4);
            float4 sv = *reinterpret_cast<const float4*>(g_sw + sl * 4);
            float4 cv = *reinterpret_cast<const float4*>(g_c + sl * 4);
            dm += xv.x * sv.x + xv.y * sv.y + xv.z * sv.z + xv.w * sv.w;
            dc += xv.x * cv.x + xv.y * cv.y + xv.z * cv.z + xv.w * cv.w;
        }
        sm[MEAN_OFF + r] = (dm + g_db[1]) * (1.0f / OUT);
        sm[DOTC_OFF + r] = dc;
    }

    // ---- stats chunk: Z = x' @ G ; rsq = sum Z .* x' per row ----
    {
        float acc[2][4][4];
        compute_chunk(xs, g_G, m0, n0, g, tig, lane, acc);

        float rsq[4] = {0.f, 0.f, 0.f, 0.f};
        #pragma unroll
        for (int mt = 0; mt < 2; ++mt)
            #pragma unroll
            for (int h = 0; h < 2; ++h) {
                const int r = m0 + mt * 16 + h * 8 + g;
                #pragma unroll
                for (int nt = 0; nt < 4; ++nt)
                    #pragma unroll
                    for (int p = 0; p < 2; ++p) {
                        int col = n0 + nt * 8 + tig * 2 + p;
                        rsq[mt * 2 + h] += acc[mt][nt][h * 2 + p] * xs[xoff_perm(r, col)];
                    }
            }
        #pragma unroll
        for (int j = 0; j < 4; ++j) {
            rsq[j] += __shfl_xor_sync(0xffffffffu, rsq[j], 1);
            rsq[j] += __shfl_xor_sync(0xffffffffu, rsq[j], 2);
        }
        if (tig == 0) {
            #pragma unroll
            for (int j = 0; j < 4; ++j) {
                int r = m0 + (j >> 1) * 16 + (j & 1) * 8 + g;
                atomicAdd(&sm[SQ_OFF + r], rsq[j]);
            }
        }
    }
    __syncthreads();

    if (tid < MTILE) {
        float sumsq = sm[SQ_OFF + tid] + 2.0f * sm[DOTC_OFF + tid] + g_db[0];
        float mean  = sm[MEAN_OFF + tid];
        float var   = sumsq * (1.0f / OUT) - mean * mean;
        sm[ISTD_OFF + tid] = rsqrtf(var + 1e-5f);
    }
    __syncthreads();

    // Per-lane epilogue row constants (iteration j covers rows j*4 + (lane>>3)).
    const int rl = lane >> 3;       // 0..3
    const int cl = (lane & 7) * 4;  // 0,4,...,28
    float meanv[8], istdv[8];
    #pragma unroll
    for (int j = 0; j < 8; ++j) {
        int r = m0 + j * 4 + rl;
        meanv[j] = sm[MEAN_OFF + r];
        istdv[j] = sm[ISTD_OFF + r];
    }

    // ---------------- main loop: 16 chunks, NO CTA barriers ----------------
    #pragma unroll 1
    for (int ch = 0; ch < NCHUNKS; ++ch) {
        float acc[2][4][4];
        compute_chunk(xs, g_wp + (size_t)ch * NCHUNK * IN, m0, n0, g, tig, lane, acc);

        // Stage the 32x32 acc tile into warp-private smem (conflict-free).
        #pragma unroll
        for (int mt = 0; mt < 2; ++mt)
            #pragma unroll
            for (int h = 0; h < 2; ++h)
                #pragma unroll
                for (int nt = 0; nt < 4; ++nt) {
                    float2 v = make_float2(acc[mt][nt][h * 2 + 0], acc[mt][nt][h * 2 + 1]);
                    *reinterpret_cast<float2*>(
                        st + (mt * 16 + h * 8 + g) * SSTR + nt * 8 + tig * 2) = v;
                }
        __syncwarp();

        // Coalesced readback + fused epilogue (float4, 4 lines/instr).
        const int cbase = ch * NCHUNK + n0;
        float4 lbv = __ldg(reinterpret_cast<const float4*>(lb + cbase + cl));
        float4 nwv = __ldg(reinterpret_cast<const float4*>(nw + cbase + cl));
        float4 nbv = __ldg(reinterpret_cast<const float4*>(nb + cbase + cl));

        #pragma unroll
        for (int j = 0; j < 8; ++j) {
            const int r = j * 4 + rl;
            float4 v = *reinterpret_cast<const float4*>(st + r * SSTR + cl);
            const size_t grow = row0 + (size_t)(m0 + r);
            float4 yv = __ldg(reinterpret_cast<const float4*>(y + grow * OUT + cbase + cl));
            const float mean = meanv[j], istd = istdv[j];
            float4 ov;
            float nm;
            nm = ((v.x + lbv.x) - mean) * istd * nwv.x + nbv.x; ov.x = (nm + yv.x) * yv.x;
            nm = ((v.y + lbv.y) - mean) * istd * nwv.y + nbv.y; ov.y = (nm + yv.y) * yv.y;
            nm = ((v.z + lbv.z) - mean) * istd * nwv.z + nbv.z; ov.z = (nm + yv.z) * yv.z;
            nm = ((v.w + lbv.w) - mean) * istd * nwv.w + nbv.w; ov.w = (nm + yv.w) * yv.w;
            *reinterpret_cast<float4*>(out + grow * OUT + cbase + cl) = ov;
        }
        __syncwarp();   // stage buffer reusable next chunk
    }
}

extern "C" void kernel_launch(void* const* d_in, const int* in_sizes, int n_in,
                              void* d_out, int out_size) {
    (void)n_in; (void)out_size;
    const float* x  = (const float*)d_in[0];
    const float* y  = (const float*)d_in[1];
    const float* w  = (const float*)d_in[2];
    const float* lb = (const float*)d_in[3];
    const float* nw = (const float*)d_in[4];
    const float* nb = (const float*)d_in[5];
    float* out = (float*)d_out;

    const int rows = in_sizes[0] / IN;   // 32768
    const int grid = rows / MTILE;       // 512

    zero_scratch_kernel<<<64, 256>>>();
    gram_kernel<<<OUT / 32, 256>>>(w, lb);
    fused_lin_inorm_kernel<<<grid, THREADS>>>(x, y, lb, nw, nb, out);
}